// round 14
// baseline (speedup 1.0000x reference)
#include <cuda_runtime.h>
#include <math.h>

#define NODE   5
#define FML    64
#define F0C    256
#define FOC    256
#define TSTEPS 128
#define BTOT   8192
#define MROWS  64
#define NCTA   (BTOT / MROWS)   // 128
#define NTHR   256
#define BN_EPS 1e-5f

// Scratch (static device arrays: allocation-free)
__device__ float g_h[BTOT * FOC];              // post-ReLU head activations
__device__ float g_stats[2 * FOC];             // sum / sumsq
__device__ float g_xT[TSTEPS * NODE * BTOT];   // x transposed to [t][n][b]

// Duplicated weights in lane-major layout:
// 256-col layers: [k][w<8][cg<4][16]  (16 floats = 8 cols x {dup,dup})
// offset for col c = (c>>5)*64 + ((c>>3)&3)*16 + (c&7)*2 + j
__device__ __align__(16) float Wd1[NODE * 130 * 512];
__device__ __align__(16) float Wd2[NODE * 256 * 512];
__device__ __align__(16) float Wd3[NODE * 256 * 128];  // 64-col: [k][w<8][cg<4][4]
__device__ __align__(16) float Wdo[325 * 512];         // rows 0..4 = x part

__device__ __host__ __forceinline__ constexpr int par0(int n) {
    return n == 0 ? 3 : n == 1 ? 0 : n == 2 ? 0 : n == 3 ? 1 : 2;
}
__device__ __host__ __forceinline__ constexpr int par1(int n) {
    return n == 0 ? 4 : n == 1 ? 4 : n == 2 ? 1 : n == 3 ? 2 : 3;
}

typedef unsigned long long u64;

// ALL activations stored TRANSPOSED: [feature][row]
struct Smem {
    float slot[6][FML][MROWS];   // 98304 B : rotating state arena, transposed
    float h1[F0C][MROWS];        // 65536 B : transposed (BN 'red' overlays at head)
    float h2[F0C][MROWS];        // 65536 B : transposed
    float xs[NODE][MROWS];       //  1280 B
};                               // 230656 B  (<= 227 KB)

__device__ __forceinline__ void ffma2(u64& d, u64 a, u64 b) {
    asm("fma.rn.f32x2 %0, %1, %2, %0;" : "+l"(d) : "l"(a), "l"(b));
}

struct B8 { ulonglong2 a, b, c, d; };   // 16 dup'd floats = 8 col-pairs
__device__ __forceinline__ B8 ldB8(const float* __restrict__ p) {
    B8 r;
    r.a = *(const ulonglong2*)(p);
    r.b = *(const ulonglong2*)(p + 4);
    r.c = *(const ulonglong2*)(p + 8);
    r.d = *(const ulonglong2*)(p + 12);
    return r;
}

// one k: acc[4 rowpairs][8 cols] += A_T[k][r0..r0+7] (x) Bdup[k][cols]
__device__ __forceinline__ void fstep8(u64 (&acc)[4][8],
    const float* __restrict__ Ak, const B8& b)
{
    const ulonglong2 pa = *(const ulonglong2*)(Ak);
    const ulonglong2 pb = *(const ulonglong2*)(Ak + 4);
    const u64 p[4] = {pa.x, pa.y, pb.x, pb.y};
#pragma unroll
    for (int rp = 0; rp < 4; ++rp) {
        ffma2(acc[rp][0], p[rp], b.a.x); ffma2(acc[rp][1], p[rp], b.a.y);
        ffma2(acc[rp][2], p[rp], b.b.x); ffma2(acc[rp][3], p[rp], b.b.y);
        ffma2(acc[rp][4], p[rp], b.c.x); ffma2(acc[rp][5], p[rp], b.c.y);
        ffma2(acc[rp][6], p[rp], b.d.x); ffma2(acc[rp][7], p[rp], b.d.y);
    }
}

// K-loop, A transposed (k-stride 64), B dup'd (k-stride 512), pair-prefetched
__device__ __forceinline__ void mac_T8(u64 (&acc)[4][8],
    const float* __restrict__ A, const float* __restrict__ B, int K)
{
    B8 u0 = ldB8(B);
    B8 u1 = ldB8(B + 512);
#pragma unroll 2
    for (int k = 0; k < K; k += 2) {
        const int kn = (k + 2 < K) ? k + 2 : k;
        B8 v0 = ldB8(B + (size_t)kn * 512);
        B8 v1 = ldB8(B + (size_t)(kn + 1) * 512);
        fstep8(acc, A + (size_t)k * 64, u0);
        fstep8(acc, A + (size_t)(k + 1) * 64, u1);
        u0 = v0; u1 = v1;
    }
}

// L3 variant: 2 cols per lane
__device__ __forceinline__ void fstep2(u64 (&acc)[4][2],
    const float* __restrict__ Ak, ulonglong2 b)
{
    const ulonglong2 pa = *(const ulonglong2*)(Ak);
    const ulonglong2 pb = *(const ulonglong2*)(Ak + 4);
    const u64 p[4] = {pa.x, pa.y, pb.x, pb.y};
#pragma unroll
    for (int rp = 0; rp < 4; ++rp) {
        ffma2(acc[rp][0], p[rp], b.x);
        ffma2(acc[rp][1], p[rp], b.y);
    }
}

__device__ __forceinline__ void mac_T2(u64 (&acc)[4][2],
    const float* __restrict__ A, const float* __restrict__ B, int K)
{
    ulonglong2 u0 = *(const ulonglong2*)(B);
    ulonglong2 u1 = *(const ulonglong2*)(B + 128);
#pragma unroll 2
    for (int k = 0; k < K; k += 2) {
        const int kn = (k + 2 < K) ? k + 2 : k;
        ulonglong2 v0 = *(const ulonglong2*)(B + (size_t)kn * 128);
        ulonglong2 v1 = *(const ulonglong2*)(B + (size_t)(kn + 1) * 128);
        fstep2(acc, A + (size_t)k * 64, u0);
        fstep2(acc, A + (size_t)(k + 1) * 64, u1);
        u0 = v0; u1 = v1;
    }
}

__device__ __forceinline__ void zero8(u64 (&acc)[4][8]) {
#pragma unroll
    for (int rp = 0; rp < 4; ++rp)
#pragma unroll
        for (int c = 0; c < 8; ++c) acc[rp][c] = 0ull;
}

// bias + ReLU + transposed store (dstT points at col c0, row 0; col stride 64)
__device__ __forceinline__ void epi_relu(const u64 (&acc)[4][8],
    const float* __restrict__ bias, float* __restrict__ dstT, int r0)
{
    const float4 q0 = *(const float4*)(bias);
    const float4 q1 = *(const float4*)(bias + 4);
    const float bb[8] = {q0.x, q0.y, q0.z, q0.w, q1.x, q1.y, q1.z, q1.w};
#pragma unroll
    for (int c = 0; c < 8; ++c) {
        union { u64 u[4]; float v[8]; } t;
        t.u[0] = acc[0][c]; t.u[1] = acc[1][c];
        t.u[2] = acc[2][c]; t.u[3] = acc[3][c];
        float4 o0, o1;
        o0.x = fmaxf(t.v[0] + bb[c], 0.f); o0.y = fmaxf(t.v[1] + bb[c], 0.f);
        o0.z = fmaxf(t.v[2] + bb[c], 0.f); o0.w = fmaxf(t.v[3] + bb[c], 0.f);
        o1.x = fmaxf(t.v[4] + bb[c], 0.f); o1.y = fmaxf(t.v[5] + bb[c], 0.f);
        o1.z = fmaxf(t.v[6] + bb[c], 0.f); o1.w = fmaxf(t.v[7] + bb[c], 0.f);
        *(float4*)(dstT + (size_t)c * 64 + r0)     = o0;
        *(float4*)(dstT + (size_t)c * 64 + r0 + 4) = o1;
    }
}

// ---------- prep: duplicate weights (lane-major), transpose x, zero stats ----------
__global__ void prep_kernel(const float* __restrict__ x,
                            const float* __restrict__ W1, const float* __restrict__ W2,
                            const float* __restrict__ W3, const float* __restrict__ Wo1)
{
    const int i = blockIdx.x * blockDim.x + threadIdx.x;
    const int stride = gridDim.x * blockDim.x;

    for (int idx = i; idx < NODE * 130 * 512; idx += stride) {
        const int d = idx & 511;
        const int nk = idx >> 9, k = nk % 130, n = nk / 130;
        const int c = (d >> 6) * 32 + ((d >> 4) & 3) * 8 + ((d & 15) >> 1);
        Wd1[idx] = W1[(size_t)n * 130 * 256 + k * 256 + c];
    }
    for (int idx = i; idx < NODE * 256 * 512; idx += stride) {
        const int d = idx & 511;
        const int nk = idx >> 9, k = nk & 255, n = nk >> 8;
        const int c = (d >> 6) * 32 + ((d >> 4) & 3) * 8 + ((d & 15) >> 1);
        Wd2[idx] = W2[(size_t)n * 65536 + k * 256 + c];
    }
    for (int idx = i; idx < NODE * 256 * 128; idx += stride) {
        const int d = idx & 127;
        const int nk = idx >> 7, k = nk & 255, n = nk >> 8;
        const int c = (d >> 4) * 8 + ((d >> 2) & 3) * 2 + ((d & 3) >> 1);
        Wd3[idx] = W3[(size_t)n * 16384 + k * 64 + c];
    }
    for (int idx = i; idx < 325 * 512; idx += stride) {
        const int d = idx & 511, k = idx >> 9;
        const int c = (d >> 6) * 32 + ((d >> 4) & 3) * 8 + ((d & 15) >> 1);
        Wdo[idx] = Wo1[(size_t)k * 256 + c];
    }
    for (int idx = i; idx < TSTEPS * NODE * BTOT; idx += stride) {
        const int b = idx & (BTOT - 1), nt = idx >> 13;
        const int n = nt % NODE, t = nt / NODE;
        g_xT[idx] = x[(size_t)b * (NODE * TSTEPS) + n * TSTEPS + t];
    }
    if (i < 2 * FOC) g_stats[i] = 0.0f;
}

__global__ __launch_bounds__(NTHR, 1)
void rnn_kernel(const float* __restrict__ b1, const float* __restrict__ b2,
                const float* __restrict__ b3, const float* __restrict__ bo1)
{
    extern __shared__ char smem_raw[];
    Smem& S = *reinterpret_cast<Smem*>(smem_raw);
    const int tid = threadIdx.x;
    const int tx  = tid & 31;
    const int w   = tid >> 5;          // warp -> 32-col slice
    const int cg  = tx & 3;
    const int rg  = tx >> 2;
    const int r0  = rg * 8;            // lane's 8 rows (4 pairs)
    const int c0  = w * 32 + cg * 8;   // lane's 8 cols (256-wide layers)
    const int wo8 = w * 64 + cg * 16;  // dup-layout offset, 256-wide
    const int c3  = w * 8 + cg * 2;    // lane's 2 cols (L3)
    const int wo2 = w * 16 + cg * 4;   // dup-layout offset, 64-wide
    const int b0  = blockIdx.x * MROWS;

    for (int i = tid; i < 6 * FML * MROWS; i += NTHR)
        (&S.slot[0][0][0])[i] = 0.0f;
    __syncthreads();

    int sl[6] = {0, 1, 2, 3, 4, 5};

    for (int t = 0; t < TSTEPS; ++t) {
        for (int i = tid; i < NODE * MROWS; i += NTHR) {
            const int n = i >> 6, r = i & 63;
            S.xs[n][r] = g_xT[((size_t)t * NODE + n) * BTOT + b0 + r];
        }
        __syncthreads();

#pragma unroll
        for (int n = 0; n < NODE; ++n) {
            const int p0 = par0(n), p1 = par1(n);
            const float* Wd1n = Wd1 + (size_t)n * 130 * 512;

            // ---------- Layer 1: inp(130) -> 256, ReLU -> h1_T ----------
            u64 acc[4][8];
            zero8(acc);
            fstep8(acc, &S.xs[p0][r0], ldB8(Wd1n + wo8));          // k=0: x p0
            fstep8(acc, &S.xs[p1][r0], ldB8(Wd1n + 512 + wo8));    // k=1: x p1
            mac_T8(acc, &S.slot[sl[p0]][0][r0], Wd1n + (size_t)2 * 512 + wo8, 64);
            mac_T8(acc, &S.slot[sl[p1]][0][r0], Wd1n + (size_t)66 * 512 + wo8, 64);
            epi_relu(acc, b1 + n * 256 + c0, &S.h1[c0][0], r0);
            __syncthreads();

            // ---------- Layer 2: 256 -> 256, ReLU -> h2_T ----------
            zero8(acc);
            mac_T8(acc, &S.h1[0][r0], Wd2 + (size_t)n * 256 * 512 + wo8, 256);
            epi_relu(acc, b2 + n * 256 + c0, &S.h2[c0][0], r0);
            __syncthreads();

            // ---------- Layer 3: 256 -> 64, tanh -> state slot (transposed) ----------
            {
                u64 a2[4][2];
#pragma unroll
                for (int rp = 0; rp < 4; ++rp) { a2[rp][0] = 0ull; a2[rp][1] = 0ull; }
                mac_T2(a2, &S.h2[0][r0], Wd3 + (size_t)n * 256 * 128 + wo2, 256);
                const int ds = (n == 0) ? sl[5] : (n == 1) ? sl[4] : sl[n - 2];
                float* dst = &S.slot[ds][0][0];
#pragma unroll
                for (int c = 0; c < 2; ++c) {
                    union { u64 u[4]; float v[8]; } tt;
                    tt.u[0] = a2[0][c]; tt.u[1] = a2[1][c];
                    tt.u[2] = a2[2][c]; tt.u[3] = a2[3][c];
                    const float bc = b3[n * 64 + c3 + c];
                    float4 o0, o1;
                    o0.x = tanhf(tt.v[0] + bc); o0.y = tanhf(tt.v[1] + bc);
                    o0.z = tanhf(tt.v[2] + bc); o0.w = tanhf(tt.v[3] + bc);
                    o1.x = tanhf(tt.v[4] + bc); o1.y = tanhf(tt.v[5] + bc);
                    o1.z = tanhf(tt.v[6] + bc); o1.w = tanhf(tt.v[7] + bc);
                    *(float4*)(dst + (size_t)(c3 + c) * 64 + r0)     = o0;
                    *(float4*)(dst + (size_t)(c3 + c) * 64 + r0 + 4) = o1;
                }
            }
            __syncthreads();
        }

        {   // rotate slot map
            const int t0 = sl[0], t1 = sl[1], t2 = sl[2];
            const int t3 = sl[3], t4 = sl[4], t5 = sl[5];
            sl[0] = t5; sl[1] = t4; sl[2] = t0;
            sl[3] = t1; sl[4] = t2; sl[5] = t3;
        }
    }

    // ---------- Head GEMM: feat(325) @ Wo1 -> ReLU -> g_h + BN partials ----------
    float* red = &S.h1[0][0];
    for (int i = tid; i < 2 * FOC; i += NTHR) red[i] = 0.0f;
    __syncthreads();

    {
        u64 acc[4][8];
        zero8(acc);
#pragma unroll
        for (int n = 0; n < NODE; ++n)   // state part (rows 5 + 64n)
            mac_T8(acc, &S.slot[sl[n]][0][r0],
                   Wdo + (size_t)(5 + 64 * n) * 512 + wo8, 64);
#pragma unroll
        for (int n = 0; n < NODE; ++n)   // x part (rows 0..4); xs holds t=T-1
            fstep8(acc, &S.xs[n][r0], ldB8(Wdo + (size_t)n * 512 + wo8));

        const float4 q0 = *(const float4*)(bo1 + c0);
        const float4 q1 = *(const float4*)(bo1 + c0 + 4);
        const float bb[8] = {q0.x, q0.y, q0.z, q0.w, q1.x, q1.y, q1.z, q1.w};
        float cs[8] = {0,0,0,0,0,0,0,0};
        float cq[8] = {0,0,0,0,0,0,0,0};
#pragma unroll
        for (int rp = 0; rp < 4; ++rp) {
            float lo[8], hi[8];
#pragma unroll
            for (int c = 0; c < 8; ++c) {
                union { u64 u; float v[2]; } e; e.u = acc[rp][c];
                lo[c] = fmaxf(e.v[0] + bb[c], 0.f);
                hi[c] = fmaxf(e.v[1] + bb[c], 0.f);
                cs[c] += lo[c] + hi[c];
                cq[c] += lo[c] * lo[c] + hi[c] * hi[c];
            }
            const size_t ro = (size_t)(b0 + r0 + 2 * rp) * FOC + c0;
            *(float4*)&g_h[ro]           = make_float4(lo[0], lo[1], lo[2], lo[3]);
            *(float4*)&g_h[ro + 4]       = make_float4(lo[4], lo[5], lo[6], lo[7]);
            *(float4*)&g_h[ro + FOC]     = make_float4(hi[0], hi[1], hi[2], hi[3]);
            *(float4*)&g_h[ro + FOC + 4] = make_float4(hi[4], hi[5], hi[6], hi[7]);
        }
#pragma unroll
        for (int j = 0; j < 8; ++j) {
            atomicAdd(&red[c0 + j],       cs[j]);
            atomicAdd(&red[FOC + c0 + j], cq[j]);
        }
    }
    __syncthreads();
    if (tid < FOC) {
        atomicAdd(&g_stats[tid],       red[tid]);
        atomicAdd(&g_stats[FOC + tid], red[FOC + tid]);
    }
}

// ---------- BN + logits + softmax ----------
__global__ __launch_bounds__(256)
void head_kernel(const float* __restrict__ gamma, const float* __restrict__ beta,
                 const float* __restrict__ Wo2, const float* __restrict__ bo2,
                 float* __restrict__ out)
{
    __shared__ float s_scale[FOC];
    __shared__ float s_shift[FOC];
    __shared__ float s_w[FOC * 7];
    __shared__ float s_b[7];
    const int tid = threadIdx.x;

    if (tid < FOC) {
        const float inv = 1.0f / (float)BTOT;
        float mu  = g_stats[tid] * inv;
        float var = g_stats[FOC + tid] * inv - mu * mu;
        float sc  = gamma[tid] * rsqrtf(var + BN_EPS);
        s_scale[tid] = sc;
        s_shift[tid] = beta[tid] - mu * sc;
    }
    for (int i = tid; i < FOC * 7; i += 256) s_w[i] = Wo2[i];
    if (tid < 7) s_b[tid] = bo2[tid];
    __syncthreads();

    const int lane = tid & 31;
    const int warp = tid >> 5;
    const int row  = blockIdx.x * 8 + warp;

    float l[7] = {0, 0, 0, 0, 0, 0, 0};
#pragma unroll
    for (int ii = 0; ii < 8; ++ii) {
        const int c = lane + 32 * ii;
        const float v  = g_h[(size_t)row * FOC + c];
        const float hn = fmaf(v, s_scale[c], s_shift[c]);
#pragma unroll
        for (int j = 0; j < 7; ++j) l[j] = fmaf(hn, s_w[c * 7 + j], l[j]);
    }
#pragma unroll
    for (int off = 16; off > 0; off >>= 1) {
#pragma unroll
        for (int j = 0; j < 7; ++j) l[j] += __shfl_xor_sync(0xFFFFFFFFu, l[j], off);
    }
    if (lane == 0) {
        float m = -1e30f;
#pragma unroll
        for (int j = 0; j < 7; ++j) { l[j] += s_b[j]; m = fmaxf(m, l[j]); }
        float e[7], sum = 0.f;
#pragma unroll
        for (int j = 0; j < 7; ++j) { e[j] = expf(l[j] - m); sum += e[j]; }
        const float r = 1.0f / sum;
#pragma unroll
        for (int j = 0; j < 7; ++j) out[(size_t)row * 7 + j] = e[j] * r;
    }
}

extern "C" void kernel_launch(void* const* d_in, const int* in_sizes, int n_in,
                              void* d_out, int out_size)
{
    (void)in_sizes; (void)n_in; (void)out_size;
    const float* x    = (const float*)d_in[0];
    const float* W1   = (const float*)d_in[1];
    const float* b1   = (const float*)d_in[2];
    const float* W2   = (const float*)d_in[3];
    const float* b2   = (const float*)d_in[4];
    const float* W3   = (const float*)d_in[5];
    const float* b3   = (const float*)d_in[6];
    const float* Wo1  = (const float*)d_in[7];
    const float* bo1  = (const float*)d_in[8];
    const float* gam  = (const float*)d_in[9];
    const float* bet  = (const float*)d_in[10];
    const float* Wo2  = (const float*)d_in[11];
    const float* bo2  = (const float*)d_in[12];
    float* out = (float*)d_out;

    cudaFuncSetAttribute(rnn_kernel, cudaFuncAttributeMaxDynamicSharedMemorySize,
                         (int)sizeof(Smem));

    prep_kernel<<<512, 256>>>(x, W1, W2, W3, Wo1);
    rnn_kernel<<<NCTA, NTHR, sizeof(Smem)>>>(b1, b2, b3, bo1);
    head_kernel<<<BTOT / 8, 256>>>(gam, bet, Wo2, bo2, out);
}

// round 15
// speedup vs baseline: 1.0494x; 1.0494x over previous
#include <cuda_runtime.h>
#include <math.h>

#define NODE   5
#define FML    64
#define F0C    256
#define FOC    256
#define TSTEPS 128
#define BTOT   8192
#define MROWS  64
#define NCTA   (BTOT / MROWS)   // 128
#define NTHR   256
#define BN_EPS 1e-5f

// Scratch (static device arrays: allocation-free)
__device__ float g_h[BTOT * FOC];              // post-ReLU head activations
__device__ float g_stats[2 * FOC];             // sum / sumsq
__device__ float g_xT[TSTEPS * NODE * BTOT];   // x transposed to [t][n][b]

// Duplicated weights in lane-major layout:
// 256-col layers: [k][w<8][cg<4][16]  (16 floats = 8 cols x {dup,dup})
// offset for col c = (c>>5)*64 + ((c>>3)&3)*16 + (c&7)*2 + j
__device__ __align__(16) float Wd1[NODE * 130 * 512];
__device__ __align__(16) float Wd2[NODE * 256 * 512];
__device__ __align__(16) float Wd3[NODE * 256 * 128];  // 64-col: [k][w<8][cg<4][4]
__device__ __align__(16) float Wdo[325 * 512];         // rows 0..4 = x part

__device__ __host__ __forceinline__ constexpr int par0(int n) {
    return n == 0 ? 3 : n == 1 ? 0 : n == 2 ? 0 : n == 3 ? 1 : 2;
}
__device__ __host__ __forceinline__ constexpr int par1(int n) {
    return n == 0 ? 4 : n == 1 ? 4 : n == 2 ? 1 : n == 3 ? 2 : 3;
}

typedef unsigned long long u64;

// ALL activations stored TRANSPOSED: [feature][row]
struct Smem {
    float slot[6][FML][MROWS];   // 98304 B : rotating state arena, transposed
    float h1[F0C][MROWS];        // 65536 B : transposed (BN 'red' overlays at head)
    float h2[F0C][MROWS];        // 65536 B : transposed
    float xs[NODE][MROWS];       //  1280 B
};                               // 230656 B  (<= 227 KB)

__device__ __forceinline__ void ffma2(u64& d, u64 a, u64 b) {
    asm("fma.rn.f32x2 %0, %1, %2, %0;" : "+l"(d) : "l"(a), "l"(b));
}

struct B8 { ulonglong2 a, b, c, d; };   // 16 dup'd floats = 8 col-pairs
__device__ __forceinline__ B8 ldB8(const float* __restrict__ p) {
    B8 r;
    r.a = *(const ulonglong2*)(p);
    r.b = *(const ulonglong2*)(p + 4);
    r.c = *(const ulonglong2*)(p + 8);
    r.d = *(const ulonglong2*)(p + 12);
    return r;
}

// one k: acc[4 rowpairs][8 cols] += A_T[k][r0..r0+7] (x) Bdup[k][cols]
__device__ __forceinline__ void fstep8(u64 (&acc)[4][8],
    const float* __restrict__ Ak, const B8& b)
{
    const ulonglong2 pa = *(const ulonglong2*)(Ak);
    const ulonglong2 pb = *(const ulonglong2*)(Ak + 4);
    const u64 p[4] = {pa.x, pa.y, pb.x, pb.y};
#pragma unroll
    for (int rp = 0; rp < 4; ++rp) {
        ffma2(acc[rp][0], p[rp], b.a.x); ffma2(acc[rp][1], p[rp], b.a.y);
        ffma2(acc[rp][2], p[rp], b.b.x); ffma2(acc[rp][3], p[rp], b.b.y);
        ffma2(acc[rp][4], p[rp], b.c.x); ffma2(acc[rp][5], p[rp], b.c.y);
        ffma2(acc[rp][6], p[rp], b.d.x); ffma2(acc[rp][7], p[rp], b.d.y);
    }
}

// K-loop with 4-deep rolling prefetch: B for k is loaded ~3.5 k-steps (>=280cyc)
// before use, covering L2 latency. A transposed (k-stride 64), B dup'd (k-stride 512).
// K must be a multiple of 4 and >= 8 (64 / 256 here).
__device__ __forceinline__ void mac_T8(u64 (&acc)[4][8],
    const float* __restrict__ A, const float* __restrict__ B, int K)
{
    B8 b0 = ldB8(B);
    B8 b1 = ldB8(B + 512);
    B8 b2 = ldB8(B + 2 * 512);
    B8 b3 = ldB8(B + 3 * 512);
#pragma unroll 1
    for (int k = 0; k < K - 4; k += 4) {
        fstep8(acc, A + (size_t)k * 64,       b0);  b0 = ldB8(B + (size_t)(k + 4) * 512);
        fstep8(acc, A + (size_t)(k + 1) * 64, b1);  b1 = ldB8(B + (size_t)(k + 5) * 512);
        fstep8(acc, A + (size_t)(k + 2) * 64, b2);  b2 = ldB8(B + (size_t)(k + 6) * 512);
        fstep8(acc, A + (size_t)(k + 3) * 64, b3);  b3 = ldB8(B + (size_t)(k + 7) * 512);
    }
    fstep8(acc, A + (size_t)(K - 4) * 64, b0);
    fstep8(acc, A + (size_t)(K - 3) * 64, b1);
    fstep8(acc, A + (size_t)(K - 2) * 64, b2);
    fstep8(acc, A + (size_t)(K - 1) * 64, b3);
}

// L3 variant: 2 cols per lane
__device__ __forceinline__ void fstep2(u64 (&acc)[4][2],
    const float* __restrict__ Ak, ulonglong2 b)
{
    const ulonglong2 pa = *(const ulonglong2*)(Ak);
    const ulonglong2 pb = *(const ulonglong2*)(Ak + 4);
    const u64 p[4] = {pa.x, pa.y, pb.x, pb.y};
#pragma unroll
    for (int rp = 0; rp < 4; ++rp) {
        ffma2(acc[rp][0], p[rp], b.x);
        ffma2(acc[rp][1], p[rp], b.y);
    }
}

__device__ __forceinline__ void mac_T2(u64 (&acc)[4][2],
    const float* __restrict__ A, const float* __restrict__ B, int K)
{
    ulonglong2 b0 = *(const ulonglong2*)(B);
    ulonglong2 b1 = *(const ulonglong2*)(B + 128);
    ulonglong2 b2 = *(const ulonglong2*)(B + 2 * 128);
    ulonglong2 b3 = *(const ulonglong2*)(B + 3 * 128);
#pragma unroll 1
    for (int k = 0; k < K - 4; k += 4) {
        fstep2(acc, A + (size_t)k * 64,       b0);  b0 = *(const ulonglong2*)(B + (size_t)(k + 4) * 128);
        fstep2(acc, A + (size_t)(k + 1) * 64, b1);  b1 = *(const ulonglong2*)(B + (size_t)(k + 5) * 128);
        fstep2(acc, A + (size_t)(k + 2) * 64, b2);  b2 = *(const ulonglong2*)(B + (size_t)(k + 6) * 128);
        fstep2(acc, A + (size_t)(k + 3) * 64, b3);  b3 = *(const ulonglong2*)(B + (size_t)(k + 7) * 128);
    }
    fstep2(acc, A + (size_t)(K - 4) * 64, b0);
    fstep2(acc, A + (size_t)(K - 3) * 64, b1);
    fstep2(acc, A + (size_t)(K - 2) * 64, b2);
    fstep2(acc, A + (size_t)(K - 1) * 64, b3);
}

__device__ __forceinline__ void zero8(u64 (&acc)[4][8]) {
#pragma unroll
    for (int rp = 0; rp < 4; ++rp)
#pragma unroll
        for (int c = 0; c < 8; ++c) acc[rp][c] = 0ull;
}

// bias + ReLU + transposed store (dstT points at col c0, row 0; col stride 64)
__device__ __forceinline__ void epi_relu(const u64 (&acc)[4][8],
    const float* __restrict__ bias, float* __restrict__ dstT, int r0)
{
    const float4 q0 = *(const float4*)(bias);
    const float4 q1 = *(const float4*)(bias + 4);
    const float bb[8] = {q0.x, q0.y, q0.z, q0.w, q1.x, q1.y, q1.z, q1.w};
#pragma unroll
    for (int c = 0; c < 8; ++c) {
        union { u64 u[4]; float v[8]; } t;
        t.u[0] = acc[0][c]; t.u[1] = acc[1][c];
        t.u[2] = acc[2][c]; t.u[3] = acc[3][c];
        float4 o0, o1;
        o0.x = fmaxf(t.v[0] + bb[c], 0.f); o0.y = fmaxf(t.v[1] + bb[c], 0.f);
        o0.z = fmaxf(t.v[2] + bb[c], 0.f); o0.w = fmaxf(t.v[3] + bb[c], 0.f);
        o1.x = fmaxf(t.v[4] + bb[c], 0.f); o1.y = fmaxf(t.v[5] + bb[c], 0.f);
        o1.z = fmaxf(t.v[6] + bb[c], 0.f); o1.w = fmaxf(t.v[7] + bb[c], 0.f);
        *(float4*)(dstT + (size_t)c * 64 + r0)     = o0;
        *(float4*)(dstT + (size_t)c * 64 + r0 + 4) = o1;
    }
}

// ---------- prep: duplicate weights (lane-major), transpose x, zero stats ----------
__global__ void prep_kernel(const float* __restrict__ x,
                            const float* __restrict__ W1, const float* __restrict__ W2,
                            const float* __restrict__ W3, const float* __restrict__ Wo1)
{
    const int i = blockIdx.x * blockDim.x + threadIdx.x;
    const int stride = gridDim.x * blockDim.x;

    for (int idx = i; idx < NODE * 130 * 512; idx += stride) {
        const int d = idx & 511;
        const int nk = idx >> 9, k = nk % 130, n = nk / 130;
        const int c = (d >> 6) * 32 + ((d >> 4) & 3) * 8 + ((d & 15) >> 1);
        Wd1[idx] = W1[(size_t)n * 130 * 256 + k * 256 + c];
    }
    for (int idx = i; idx < NODE * 256 * 512; idx += stride) {
        const int d = idx & 511;
        const int nk = idx >> 9, k = nk & 255, n = nk >> 8;
        const int c = (d >> 6) * 32 + ((d >> 4) & 3) * 8 + ((d & 15) >> 1);
        Wd2[idx] = W2[(size_t)n * 65536 + k * 256 + c];
    }
    for (int idx = i; idx < NODE * 256 * 128; idx += stride) {
        const int d = idx & 127;
        const int nk = idx >> 7, k = nk & 255, n = nk >> 8;
        const int c = (d >> 4) * 8 + ((d >> 2) & 3) * 2 + ((d & 3) >> 1);
        Wd3[idx] = W3[(size_t)n * 16384 + k * 64 + c];
    }
    for (int idx = i; idx < 325 * 512; idx += stride) {
        const int d = idx & 511, k = idx >> 9;
        const int c = (d >> 6) * 32 + ((d >> 4) & 3) * 8 + ((d & 15) >> 1);
        Wdo[idx] = Wo1[(size_t)k * 256 + c];
    }
    for (int idx = i; idx < TSTEPS * NODE * BTOT; idx += stride) {
        const int b = idx & (BTOT - 1), nt = idx >> 13;
        const int n = nt % NODE, t = nt / NODE;
        g_xT[idx] = x[(size_t)b * (NODE * TSTEPS) + n * TSTEPS + t];
    }
    if (i < 2 * FOC) g_stats[i] = 0.0f;
}

__global__ __launch_bounds__(NTHR, 1)
void rnn_kernel(const float* __restrict__ b1, const float* __restrict__ b2,
                const float* __restrict__ b3, const float* __restrict__ bo1)
{
    extern __shared__ char smem_raw[];
    Smem& S = *reinterpret_cast<Smem*>(smem_raw);
    const int tid = threadIdx.x;
    const int tx  = tid & 31;
    const int w   = tid >> 5;          // warp -> 32-col slice
    const int cg  = tx & 3;
    const int rg  = tx >> 2;
    const int r0  = rg * 8;            // lane's 8 rows (4 pairs)
    const int c0  = w * 32 + cg * 8;   // lane's 8 cols (256-wide layers)
    const int wo8 = w * 64 + cg * 16;  // dup-layout offset, 256-wide
    const int c3  = w * 8 + cg * 2;    // lane's 2 cols (L3)
    const int wo2 = w * 16 + cg * 4;   // dup-layout offset, 64-wide
    const int b0  = blockIdx.x * MROWS;

    for (int i = tid; i < 6 * FML * MROWS; i += NTHR)
        (&S.slot[0][0][0])[i] = 0.0f;
    __syncthreads();

    int sl[6] = {0, 1, 2, 3, 4, 5};

    for (int t = 0; t < TSTEPS; ++t) {
        for (int i = tid; i < NODE * MROWS; i += NTHR) {
            const int n = i >> 6, r = i & 63;
            S.xs[n][r] = g_xT[((size_t)t * NODE + n) * BTOT + b0 + r];
        }
        __syncthreads();

#pragma unroll
        for (int n = 0; n < NODE; ++n) {
            const int p0 = par0(n), p1 = par1(n);
            const float* Wd1n = Wd1 + (size_t)n * 130 * 512;

            // ---------- Layer 1: inp(130) -> 256, ReLU -> h1_T ----------
            u64 acc[4][8];
            zero8(acc);
            fstep8(acc, &S.xs[p0][r0], ldB8(Wd1n + wo8));          // k=0: x p0
            fstep8(acc, &S.xs[p1][r0], ldB8(Wd1n + 512 + wo8));    // k=1: x p1
            mac_T8(acc, &S.slot[sl[p0]][0][r0], Wd1n + (size_t)2 * 512 + wo8, 64);
            mac_T8(acc, &S.slot[sl[p1]][0][r0], Wd1n + (size_t)66 * 512 + wo8, 64);
            epi_relu(acc, b1 + n * 256 + c0, &S.h1[c0][0], r0);
            __syncthreads();

            // ---------- Layer 2: 256 -> 256, ReLU -> h2_T ----------
            zero8(acc);
            mac_T8(acc, &S.h1[0][r0], Wd2 + (size_t)n * 256 * 512 + wo8, 256);
            epi_relu(acc, b2 + n * 256 + c0, &S.h2[c0][0], r0);
            __syncthreads();

            // ---------- Layer 3: 256 -> 64, tanh -> state slot (transposed) ----------
            {
                u64 a2[4][2];
#pragma unroll
                for (int rp = 0; rp < 4; ++rp) { a2[rp][0] = 0ull; a2[rp][1] = 0ull; }
                mac_T2(a2, &S.h2[0][r0], Wd3 + (size_t)n * 256 * 128 + wo2, 256);
                const int ds = (n == 0) ? sl[5] : (n == 1) ? sl[4] : sl[n - 2];
                float* dst = &S.slot[ds][0][0];
#pragma unroll
                for (int c = 0; c < 2; ++c) {
                    union { u64 u[4]; float v[8]; } tt;
                    tt.u[0] = a2[0][c]; tt.u[1] = a2[1][c];
                    tt.u[2] = a2[2][c]; tt.u[3] = a2[3][c];
                    const float bc = b3[n * 64 + c3 + c];
                    float4 o0, o1;
                    o0.x = tanhf(tt.v[0] + bc); o0.y = tanhf(tt.v[1] + bc);
                    o0.z = tanhf(tt.v[2] + bc); o0.w = tanhf(tt.v[3] + bc);
                    o1.x = tanhf(tt.v[4] + bc); o1.y = tanhf(tt.v[5] + bc);
                    o1.z = tanhf(tt.v[6] + bc); o1.w = tanhf(tt.v[7] + bc);
                    *(float4*)(dst + (size_t)(c3 + c) * 64 + r0)     = o0;
                    *(float4*)(dst + (size_t)(c3 + c) * 64 + r0 + 4) = o1;
                }
            }
            __syncthreads();
        }

        {   // rotate slot map
            const int t0 = sl[0], t1 = sl[1], t2 = sl[2];
            const int t3 = sl[3], t4 = sl[4], t5 = sl[5];
            sl[0] = t5; sl[1] = t4; sl[2] = t0;
            sl[3] = t1; sl[4] = t2; sl[5] = t3;
        }
    }

    // ---------- Head GEMM: feat(325) @ Wo1 -> ReLU -> g_h + BN partials ----------
    float* red = &S.h1[0][0];
    for (int i = tid; i < 2 * FOC; i += NTHR) red[i] = 0.0f;
    __syncthreads();

    {
        u64 acc[4][8];
        zero8(acc);
#pragma unroll
        for (int n = 0; n < NODE; ++n)   // state part (rows 5 + 64n)
            mac_T8(acc, &S.slot[sl[n]][0][r0],
                   Wdo + (size_t)(5 + 64 * n) * 512 + wo8, 64);
#pragma unroll
        for (int n = 0; n < NODE; ++n)   // x part (rows 0..4); xs holds t=T-1
            fstep8(acc, &S.xs[n][r0], ldB8(Wdo + (size_t)n * 512 + wo8));

        const float4 q0 = *(const float4*)(bo1 + c0);
        const float4 q1 = *(const float4*)(bo1 + c0 + 4);
        const float bb[8] = {q0.x, q0.y, q0.z, q0.w, q1.x, q1.y, q1.z, q1.w};
        float cs[8] = {0,0,0,0,0,0,0,0};
        float cq[8] = {0,0,0,0,0,0,0,0};
#pragma unroll
        for (int rp = 0; rp < 4; ++rp) {
            float lo[8], hi[8];
#pragma unroll
            for (int c = 0; c < 8; ++c) {
                union { u64 u; float v[2]; } e; e.u = acc[rp][c];
                lo[c] = fmaxf(e.v[0] + bb[c], 0.f);
                hi[c] = fmaxf(e.v[1] + bb[c], 0.f);
                cs[c] += lo[c] + hi[c];
                cq[c] += lo[c] * lo[c] + hi[c] * hi[c];
            }
            const size_t ro = (size_t)(b0 + r0 + 2 * rp) * FOC + c0;
            *(float4*)&g_h[ro]           = make_float4(lo[0], lo[1], lo[2], lo[3]);
            *(float4*)&g_h[ro + 4]       = make_float4(lo[4], lo[5], lo[6], lo[7]);
            *(float4*)&g_h[ro + FOC]     = make_float4(hi[0], hi[1], hi[2], hi[3]);
            *(float4*)&g_h[ro + FOC + 4] = make_float4(hi[4], hi[5], hi[6], hi[7]);
        }
#pragma unroll
        for (int j = 0; j < 8; ++j) {
            atomicAdd(&red[c0 + j],       cs[j]);
            atomicAdd(&red[FOC + c0 + j], cq[j]);
        }
    }
    __syncthreads();
    if (tid < FOC) {
        atomicAdd(&g_stats[tid],       red[tid]);
        atomicAdd(&g_stats[FOC + tid], red[FOC + tid]);
    }
}

// ---------- BN + logits + softmax ----------
__global__ __launch_bounds__(256)
void head_kernel(const float* __restrict__ gamma, const float* __restrict__ beta,
                 const float* __restrict__ Wo2, const float* __restrict__ bo2,
                 float* __restrict__ out)
{
    __shared__ float s_scale[FOC];
    __shared__ float s_shift[FOC];
    __shared__ float s_w[FOC * 7];
    __shared__ float s_b[7];
    const int tid = threadIdx.x;

    if (tid < FOC) {
        const float inv = 1.0f / (float)BTOT;
        float mu  = g_stats[tid] * inv;
        float var = g_stats[FOC + tid] * inv - mu * mu;
        float sc  = gamma[tid] * rsqrtf(var + BN_EPS);
        s_scale[tid] = sc;
        s_shift[tid] = beta[tid] - mu * sc;
    }
    for (int i = tid; i < FOC * 7; i += 256) s_w[i] = Wo2[i];
    if (tid < 7) s_b[tid] = bo2[tid];
    __syncthreads();

    const int lane = tid & 31;
    const int warp = tid >> 5;
    const int row  = blockIdx.x * 8 + warp;

    float l[7] = {0, 0, 0, 0, 0, 0, 0};
#pragma unroll
    for (int ii = 0; ii < 8; ++ii) {
        const int c = lane + 32 * ii;
        const float v  = g_h[(size_t)row * FOC + c];
        const float hn = fmaf(v, s_scale[c], s_shift[c]);
#pragma unroll
        for (int j = 0; j < 7; ++j) l[j] = fmaf(hn, s_w[c * 7 + j], l[j]);
    }
#pragma unroll
    for (int off = 16; off > 0; off >>= 1) {
#pragma unroll
        for (int j = 0; j < 7; ++j) l[j] += __shfl_xor_sync(0xFFFFFFFFu, l[j], off);
    }
    if (lane == 0) {
        float m = -1e30f;
#pragma unroll
        for (int j = 0; j < 7; ++j) { l[j] += s_b[j]; m = fmaxf(m, l[j]); }
        float e[7], sum = 0.f;
#pragma unroll
        for (int j = 0; j < 7; ++j) { e[j] = expf(l[j] - m); sum += e[j]; }
        const float r = 1.0f / sum;
#pragma unroll
        for (int j = 0; j < 7; ++j) out[(size_t)row * 7 + j] = e[j] * r;
    }
}

extern "C" void kernel_launch(void* const* d_in, const int* in_sizes, int n_in,
                              void* d_out, int out_size)
{
    (void)in_sizes; (void)n_in; (void)out_size;
    const float* x    = (const float*)d_in[0];
    const float* W1   = (const float*)d_in[1];
    const float* b1   = (const float*)d_in[2];
    const float* W2   = (const float*)d_in[3];
    const float* b2   = (const float*)d_in[4];
    const float* W3   = (const float*)d_in[5];
    const float* b3   = (const float*)d_in[6];
    const float* Wo1  = (const float*)d_in[7];
    const float* bo1  = (const float*)d_in[8];
    const float* gam  = (const float*)d_in[9];
    const float* bet  = (const float*)d_in[10];
    const float* Wo2  = (const float*)d_in[11];
    const float* bo2  = (const float*)d_in[12];
    float* out = (float*)d_out;

    cudaFuncSetAttribute(rnn_kernel, cudaFuncAttributeMaxDynamicSharedMemorySize,
                         (int)sizeof(Smem));

    prep_kernel<<<512, 256>>>(x, W1, W2, W3, Wo1);
    rnn_kernel<<<NCTA, NTHR, sizeof(Smem)>>>(b1, b2, b3, bo1);
    head_kernel<<<BTOT / 8, 256>>>(gam, bet, Wo2, bo2, out);
}